// round 14
// baseline (speedup 1.0000x reference)
#include <cuda_runtime.h>
#include <cuda_fp16.h>
#include <math.h>
#include <stdint.h>

// Problem constants
#define TOK 2048
#define DIM 1024
#define HID 4096
#define NE  8
#define NG  9
#define CAP 2048

// ---- GEMM1: CTA 128x128 dual-B, KT=64, 512 thr, warp 32x32, 4 stages ----
#define AS1 72
#define A_BY1 (128 * AS1 * 2)          // 18432
#define B_BY1 (64 * 136 * 2)           // 17408
#define STG1 (A_BY1 + 2 * B_BY1)       // 53248
#define SMEM1 (4 * STG1)               // 212992

// ---- GEMM2: CTA 128x128, KT=32, 256 thr, warp 64x32, 4 stages, 2 CTA/SM --
#define AS2 40
#define A_BY2 (128 * AS2 * 2)          // 10240
#define B_BY2 (32 * 136 * 2)           // 8704
#define STG2 (A_BY2 + B_BY2)           // 18944
#define SMEM2 (4 * STG2)               // 75776

// ---------------- device scratch ----------------
__device__ int    g_counts[NE];
__device__ int    g_rows[NE * CAP];
__device__ int    g_tok_e[TOK * 2];
__device__ int    g_tok_p[TOK * 2];
__device__ float  g_tok_w[TOK * 2];
__device__ __half g_xh[(size_t)TOK * DIM];
__device__ __half g_w1h[(size_t)NG * DIM * HID];
__device__ __half g_w2h[(size_t)NG * DIM * HID];
__device__ __half g_w3h[(size_t)NG * HID * DIM];
__device__ __half g_hh[(size_t)NG * CAP * HID];
__device__ float  g_y[(size_t)NG * CAP * DIM];

// ---------------- PTX helpers ----------------
__device__ __forceinline__ uint32_t smem_u32(const void* p) {
    uint32_t a;
    asm("{ .reg .u64 t; cvta.to.shared.u64 t, %1; cvt.u32.u64 %0, t; }"
        : "=r"(a) : "l"(p));
    return a;
}
__device__ __forceinline__ void cpa16(uint32_t dst, const void* src) {
    asm volatile("cp.async.cg.shared.global [%0], [%1], 16;"
                 :: "r"(dst), "l"(src) : "memory");
}
__device__ __forceinline__ void cpa16z(uint32_t dst, const void* src, int sz) {
    asm volatile("cp.async.cg.shared.global [%0], [%1], 16, %2;"
                 :: "r"(dst), "l"(src), "r"(sz) : "memory");
}
#define CP_COMMIT() asm volatile("cp.async.commit_group;" ::: "memory")
#define CP_WAIT(n)  asm volatile("cp.async.wait_group %0;" :: "n"(n) : "memory")

__device__ __forceinline__ void ldsm4(uint32_t* r, uint32_t addr) {
    asm volatile("ldmatrix.sync.aligned.m8n8.x4.shared.b16 {%0,%1,%2,%3}, [%4];"
                 : "=r"(r[0]), "=r"(r[1]), "=r"(r[2]), "=r"(r[3]) : "r"(addr));
}
__device__ __forceinline__ void ldsm4t(uint32_t* r, uint32_t addr) {
    asm volatile("ldmatrix.sync.aligned.m8n8.x4.trans.shared.b16 {%0,%1,%2,%3}, [%4];"
                 : "=r"(r[0]), "=r"(r[1]), "=r"(r[2]), "=r"(r[3]) : "r"(addr));
}
__device__ __forceinline__ void mma16(float* d, const uint32_t* a, const uint32_t* b) {
    asm volatile(
        "mma.sync.aligned.m16n8k16.row.col.f32.f16.f16.f32 "
        "{%0,%1,%2,%3}, {%4,%5,%6,%7}, {%8,%9}, {%0,%1,%2,%3};"
        : "+f"(d[0]), "+f"(d[1]), "+f"(d[2]), "+f"(d[3])
        : "r"(a[0]), "r"(a[1]), "r"(a[2]), "r"(a[3]), "r"(b[0]), "r"(b[1]));
}

// ---------------- 0) convert f32 -> f16 ----------------
// phase 0: segs {w1, sw1, w2, sw2, x}; phase 1: {w3, sw3}
__device__ __forceinline__ void cvt8(const float4* s4, uint4* d4, size_t i) {
    float4 a = s4[2 * i], b = s4[2 * i + 1];
    __half2 h0 = __floats2half2_rn(a.x, a.y);
    __half2 h1 = __floats2half2_rn(a.z, a.w);
    __half2 h2 = __floats2half2_rn(b.x, b.y);
    __half2 h3 = __floats2half2_rn(b.z, b.w);
    uint4 o;
    o.x = *(uint32_t*)&h0; o.y = *(uint32_t*)&h1;
    o.z = *(uint32_t*)&h2; o.w = *(uint32_t*)&h3;
    d4[i] = o;
}
__global__ __launch_bounds__(256) void convert_k(
    int phase,
    const float* __restrict__ x,
    const float* __restrict__ sw1, const float* __restrict__ sw2,
    const float* __restrict__ sw3,
    const float* __restrict__ w1, const float* __restrict__ w2,
    const float* __restrict__ w3) {
    int seg = blockIdx.y + (phase ? 5 : 0);
    const float* src; __half* dst; size_t cnt;
    switch (seg) {
        case 0: src = w1;  dst = g_w1h;                          cnt = (size_t)NE * DIM * HID; break;
        case 1: src = sw1; dst = g_w1h + (size_t)NE * DIM * HID; cnt = (size_t)DIM * HID;      break;
        case 2: src = w2;  dst = g_w2h;                          cnt = (size_t)NE * DIM * HID; break;
        case 3: src = sw2; dst = g_w2h + (size_t)NE * DIM * HID; cnt = (size_t)DIM * HID;      break;
        case 4: src = x;   dst = g_xh;                           cnt = (size_t)TOK * DIM;      break;
        case 5: src = w3;  dst = g_w3h;                          cnt = (size_t)NE * HID * DIM; break;
        default: src = sw3; dst = g_w3h + (size_t)NE * HID * DIM; cnt = (size_t)HID * DIM;     break;
    }
    size_t n8 = cnt >> 3;
    size_t i0 = (size_t)blockIdx.x * blockDim.x + threadIdx.x;
    size_t stride = (size_t)gridDim.x * blockDim.x;
    const float4* s4 = (const float4*)src;
    uint4* d4 = (uint4*)dst;
    size_t i = i0;
    for (; i + 3 * stride < n8; i += 4 * stride) {
        cvt8(s4, d4, i);
        cvt8(s4, d4, i + stride);
        cvt8(s4, d4, i + 2 * stride);
        cvt8(s4, d4, i + 3 * stride);
    }
    for (; i < n8; i += stride) cvt8(s4, d4, i);
}

// ---------------- 1) router ----------------
__global__ __launch_bounds__(256) void router_k(const float* __restrict__ x,
                                                const float* __restrict__ rw,
                                                float* __restrict__ logits) {
    int t = blockIdx.x;
    __shared__ float xs[DIM];
    __shared__ float lg[NE];
    int tid = threadIdx.x;
    for (int i = tid; i < DIM; i += 256) xs[i] = x[(size_t)t * DIM + i];
    __syncthreads();
    int w = tid >> 5, lane = tid & 31;
    const float* r = rw + w * DIM;
    float s = 0.f;
    for (int i = lane; i < DIM; i += 32) s += xs[i] * r[i];
    #pragma unroll
    for (int o = 16; o; o >>= 1) s += __shfl_down_sync(0xffffffffu, s, o);
    if (lane == 0) lg[w] = s;
    __syncthreads();
    if (tid == 0) {
        #pragma unroll
        for (int e = 0; e < NE; e++) logits[t * NE + e] = lg[e];
        int e0 = 0; float l0 = lg[0];
        for (int e = 1; e < NE; e++) if (lg[e] > l0) { l0 = lg[e]; e0 = e; }
        int e1 = -1; float l1 = -1e30f;
        for (int e = 0; e < NE; e++) if (e != e0 && lg[e] > l1) { l1 = lg[e]; e1 = e; }
        float w0 = 1.f / (1.f + __expf(l1 - l0));
        float w1 = 1.f - w0;
        int p0 = atomicAdd(&g_counts[e0], 1);
        int p1 = atomicAdd(&g_counts[e1], 1);
        g_rows[e0 * CAP + p0] = t;
        g_rows[e1 * CAP + p1] = t;
        g_tok_e[2*t] = e0; g_tok_e[2*t+1] = e1;
        g_tok_p[2*t] = p0; g_tok_p[2*t+1] = p1;
        g_tok_w[2*t] = w0; g_tok_w[2*t+1] = w1;
    }
}

// ------- 2) GEMM1 (fp16 mma, 512 thr, warp 32x32, KT=64, 4 stages) --------
__global__ __launch_bounds__(512, 1) void gemm1_tc() {
    int g = blockIdx.z;
    int n = (g == 8) ? TOK : g_counts[g];
    int row0 = blockIdx.x * 128;
    if (row0 >= n) return;
    int col0 = blockIdx.y * 128;
    const __half* B1g = g_w1h + (size_t)g * DIM * HID;
    const __half* B2g = g_w2h + (size_t)g * DIM * HID;

    extern __shared__ char dynb[];
    __shared__ int toks[128];
    int tid = threadIdx.x, lane = tid & 31, wid = tid >> 5;

    if (tid < 128) {
        int r = row0 + tid;
        toks[tid] = (r < n) ? ((g == 8) ? r : g_rows[g * CAP + r]) : -1;
    }
    __syncthreads();

    uint32_t sbase = smem_u32(dynb);
    int am = tid >> 2, aq = tid & 3;
    int atok = toks[am];
    const __half* asrc = g_xh + ((atok >= 0) ? (size_t)atok * DIM : 0) + aq * 16;
    int asz = (atok >= 0) ? 16 : 0;
    uint32_t adst = sbase + am * (AS1 * 2) + aq * 32;
    int brow = tid >> 3, bch = (tid & 7) * 2;
    const __half* b1src = B1g + (size_t)brow * HID + col0 + bch * 8;
    const __half* b2src = B2g + (size_t)brow * HID + col0 + bch * 8;
    uint32_t bdst = sbase + A_BY1 + brow * (136 * 2) + bch * 16;

    const int NC = DIM / 64;  // 16

    auto prefetch = [&](int c) {
        uint32_t so = (uint32_t)(c & 3) * STG1;
        cpa16z(adst + so,      asrc + c * 64,     asz);
        cpa16z(adst + so + 16, asrc + c * 64 + 8, asz);
        const __half* p1 = b1src + (size_t)(c * 64) * HID;
        const __half* p2 = b2src + (size_t)(c * 64) * HID;
        cpa16(bdst + so,                p1);
        cpa16(bdst + so + 16,           p1 + 8);
        cpa16(bdst + so + B_BY1,        p2);
        cpa16(bdst + so + B_BY1 + 16,   p2 + 8);
    };

    prefetch(0); CP_COMMIT();
    prefetch(1); CP_COMMIT();
    prefetch(2); CP_COMMIT();

    float acc1[2][4][4] = {};
    float acc2[2][4][4] = {};
    int wm = (wid & 3) * 32, wn = (wid >> 2) * 32;
    uint32_t aoff = ((wm + (lane & 15)) * AS1 + (lane >> 4) * 8) * 2;
    uint32_t boff = ((lane & 15) * 136 + wn + (lane >> 4) * 8) * 2;

    for (int c = 0; c < NC; c++) {
        CP_WAIT(2);
        __syncthreads();
        if (c + 3 < NC) prefetch(c + 3);
        CP_COMMIT();
        uint32_t As_u = sbase + (uint32_t)(c & 3) * STG1;
        uint32_t B1_u = As_u + A_BY1;
        uint32_t B2_u = B1_u + B_BY1;
        #pragma unroll
        for (int kk = 0; kk < 4; kk++) {
            uint32_t af[2][4];
            #pragma unroll
            for (int mf = 0; mf < 2; mf++)
                ldsm4(af[mf], As_u + aoff + mf * (16 * AS1 * 2) + kk * 32);
            #pragma unroll
            for (int nfp = 0; nfp < 2; nfp++) {
                uint32_t bb = boff + nfp * 32 + kk * (16 * 136 * 2);
                uint32_t b1[4], b2[4];
                ldsm4t(b1, B1_u + bb);
                ldsm4t(b2, B2_u + bb);
                #pragma unroll
                for (int mf = 0; mf < 2; mf++) {
                    mma16(acc1[mf][nfp * 2],     af[mf], b1);
                    mma16(acc1[mf][nfp * 2 + 1], af[mf], b1 + 2);
                    mma16(acc2[mf][nfp * 2],     af[mf], b2);
                    mma16(acc2[mf][nfp * 2 + 1], af[mf], b2 + 2);
                }
            }
        }
    }

    #pragma unroll
    for (int mf = 0; mf < 2; mf++) {
        #pragma unroll
        for (int h = 0; h < 2; h++) {
            int r = row0 + wm + mf * 16 + (lane >> 2) + h * 8;
            if (r < n) {
                __half* hp = g_hh + ((size_t)g * CAP + r) * HID + col0 + wn + (lane & 3) * 2;
                #pragma unroll
                for (int nf = 0; nf < 4; nf++) {
                    float a0 = acc1[mf][nf][h * 2], a1 = acc1[mf][nf][h * 2 + 1];
                    float s0 = a0 / (1.f + __expf(-a0));
                    float s1 = a1 / (1.f + __expf(-a1));
                    *(__half2*)(hp + nf * 8) =
                        __floats2half2_rn(s0 * acc2[mf][nf][h * 2],
                                          s1 * acc2[mf][nf][h * 2 + 1]);
                }
            }
        }
    }
}

// ------- 3) GEMM2 (fp16 mma, 256 thr, warp 64x32, KT=32, 4 st, 2 CTA) -----
__global__ __launch_bounds__(256, 2) void gemm2_tc() {
    int g = blockIdx.z;
    int n = (g == 8) ? TOK : g_counts[g];
    int row0 = blockIdx.x * 128;
    if (row0 >= n) return;
    int col0 = blockIdx.y * 128;
    const __half* Bg = g_w3h + (size_t)g * HID * DIM;

    extern __shared__ char dynb[];
    int tid = threadIdx.x, lane = tid & 31, wid = tid >> 5;
    uint32_t sbase = smem_u32(dynb);

    int am = tid >> 1, aq = (tid & 1) * 2;
    int ar = row0 + am;
    const __half* asrc = g_hh + ((ar < n) ? ((size_t)g * CAP + ar) * HID : 0) + aq * 8;
    int asz = (ar < n) ? 16 : 0;
    uint32_t adst = sbase + am * (AS2 * 2) + aq * 16;
    int brow = tid >> 3, bch = (tid & 7) * 2;
    const __half* bsrc = Bg + (size_t)brow * DIM + col0 + bch * 8;
    uint32_t bdst = sbase + A_BY2 + brow * (136 * 2) + bch * 16;

    const int NC = HID / 32;  // 128

    auto prefetch = [&](int c) {
        uint32_t so = (uint32_t)(c & 3) * STG2;
        cpa16z(adst + so,      asrc + c * 32,     asz);
        cpa16z(adst + so + 16, asrc + c * 32 + 8, asz);
        const __half* p = bsrc + (size_t)(c * 32) * DIM;
        cpa16(bdst + so,      p);
        cpa16(bdst + so + 16, p + 8);
    };

    prefetch(0); CP_COMMIT();
    prefetch(1); CP_COMMIT();
    prefetch(2); CP_COMMIT();

    float acc[4][4][4] = {};
    int wm = (wid & 1) * 64, wn = (wid >> 1) * 32;   // warp tile 64x32
    uint32_t aoff = ((wm + (lane & 15)) * AS2 + (lane >> 4) * 8) * 2;
    uint32_t boff = ((lane & 15) * 136 + wn + (lane >> 4) * 8) * 2;

    for (int c = 0; c < NC; c++) {
        CP_WAIT(2);
        __syncthreads();
        if (c + 3 < NC) prefetch(c + 3);
        CP_COMMIT();
        uint32_t As_u = sbase + (uint32_t)(c & 3) * STG2;
        uint32_t B_u  = As_u + A_BY2;
        #pragma unroll
        for (int kk = 0; kk < 2; kk++) {
            uint32_t af[4][4];
            #pragma unroll
            for (int mf = 0; mf < 4; mf++)
                ldsm4(af[mf], As_u + aoff + mf * (16 * AS2 * 2) + kk * 32);
            #pragma unroll
            for (int nfp = 0; nfp < 2; nfp++) {
                uint32_t bb = boff + nfp * 32 + kk * (16 * 136 * 2);
                uint32_t b[4];
                ldsm4t(b, B_u + bb);
                #pragma unroll
                for (int mf = 0; mf < 4; mf++) {
                    mma16(acc[mf][nfp * 2],     af[mf], b);
                    mma16(acc[mf][nfp * 2 + 1], af[mf], b + 2);
                }
            }
        }
    }

    #pragma unroll
    for (int mf = 0; mf < 4; mf++) {
        #pragma unroll
        for (int h = 0; h < 2; h++) {
            int r = row0 + wm + mf * 16 + (lane >> 2) + h * 8;
            if (r < n) {
                float* yp = g_y + ((size_t)g * CAP + r) * DIM + col0 + wn + (lane & 3) * 2;
                #pragma unroll
                for (int nf = 0; nf < 4; nf++)
                    *(float2*)(yp + nf * 8) =
                        make_float2(acc[mf][nf][h * 2], acc[mf][nf][h * 2 + 1]);
            }
        }
    }
}

// ---------------- 4) combine ----------------
__global__ __launch_bounds__(256) void combine_k(float* __restrict__ out) {
    int t = blockIdx.x;
    int tid = threadIdx.x;
    int e0 = g_tok_e[2*t], e1 = g_tok_e[2*t+1];
    int p0 = g_tok_p[2*t], p1 = g_tok_p[2*t+1];
    float w0 = g_tok_w[2*t], w1 = g_tok_w[2*t+1];
    const float4* ys = (const float4*)(g_y + ((size_t)8 * CAP + t) * DIM);
    const float4* y0 = (const float4*)(g_y + ((size_t)e0 * CAP + p0) * DIM);
    const float4* y1 = (const float4*)(g_y + ((size_t)e1 * CAP + p1) * DIM);
    float4* op = (float4*)(out + (size_t)t * DIM);
    float4 a = ys[tid], b = y0[tid], c = y1[tid];
    float4 o;
    o.x = a.x + w0 * b.x + w1 * c.x;
    o.y = a.y + w0 * b.y + w1 * c.y;
    o.z = a.z + w0 * b.z + w1 * c.z;
    o.w = a.w + w0 * b.w + w1 * c.w;
    op[tid] = o;
}

// ---------------- launch ----------------
extern "C" void kernel_launch(void* const* d_in, const int* in_sizes, int n_in,
                              void* d_out, int out_size) {
    const float* x   = (const float*)d_in[0];
    const float* sw1 = (const float*)d_in[1];
    const float* sw2 = (const float*)d_in[2];
    const float* sw3 = (const float*)d_in[3];
    const float* w1  = (const float*)d_in[4];
    const float* w2  = (const float*)d_in[5];
    const float* w3  = (const float*)d_in[6];
    const float* rw  = (const float*)d_in[7];
    float* out    = (float*)d_out;
    float* logits = out + (size_t)TOK * DIM;

    // One-time resources: created on the FIRST (correctness) call, so the
    // harness's pre-capture baseline includes them; the capture call performs
    // no allocations and teardown returns to baseline.
    static bool s_init = false;
    static cudaStream_t s2, s3;
    static cudaEvent_t eM, e1, e2, e3;
    if (!s_init) {
        cudaStreamCreateWithFlags(&s2, cudaStreamNonBlocking);
        cudaStreamCreateWithFlags(&s3, cudaStreamNonBlocking);
        cudaEventCreateWithFlags(&eM, cudaEventDisableTiming);
        cudaEventCreateWithFlags(&e1, cudaEventDisableTiming);
        cudaEventCreateWithFlags(&e2, cudaEventDisableTiming);
        cudaEventCreateWithFlags(&e3, cudaEventDisableTiming);
        cudaFuncSetAttribute(gemm1_tc, cudaFuncAttributeMaxDynamicSharedMemorySize, SMEM1);
        cudaFuncSetAttribute(gemm2_tc, cudaFuncAttributeMaxDynamicSharedMemorySize, SMEM2);
        // Warm both side streams so their internal pools are allocated NOW
        // (inside the baseline), not during capture.
        cudaMemsetAsync((void*)g_counts, 0, 1, s2);
        cudaMemsetAsync((void*)g_counts, 0, 1, s3);
        s_init = true;
    }

    void* cptr = nullptr;
    cudaGetSymbolAddress(&cptr, g_counts);
    cudaMemsetAsync(cptr, 0, NE * sizeof(int));

    // fork router (needs only f32 inputs + zeroed counts)
    cudaEventRecord(eM, 0);
    cudaStreamWaitEvent(s3, eM, 0);
    router_k<<<TOK, 256, 0, s3>>>(x, rw, logits);
    cudaEventRecord(e3, s3);

    // phase-0 convert (w1, w2, x) on main stream, full machine
    convert_k<<<dim3(432, 5), 256>>>(0, x, sw1, sw2, sw3, w1, w2, w3);

    // fork: small-grid w3 convert overlapped with gemm1 (96 CTAs, MLP-unrolled)
    cudaEventRecord(e1, 0);
    cudaStreamWaitEvent(s2, e1, 0);
    convert_k<<<dim3(48, 2), 256, 0, s2>>>(1, x, sw1, sw2, sw3, w1, w2, w3);
    cudaEventRecord(e2, s2);

    // gemm1 needs router + phase-0 convert
    cudaStreamWaitEvent(0, e3, 0);
    gemm1_tc<<<dim3(CAP / 128, HID / 128, NG), 512, SMEM1>>>();

    // join: gemm2 needs w3h
    cudaStreamWaitEvent(0, e2, 0);
    gemm2_tc<<<dim3(CAP / 128, DIM / 128, NG), 256, SMEM2>>>();
    combine_k<<<TOK, 256>>>(out);
}

// round 15
// speedup vs baseline: 1.0078x; 1.0078x over previous
#include <cuda_runtime.h>
#include <cuda_fp16.h>
#include <math.h>
#include <stdint.h>

// Problem constants
#define TOK 2048
#define DIM 1024
#define HID 4096
#define NE  8
#define NG  9
#define CAP 2048

// ---- GEMM1: CTA 128x128 dual-B, KT=64, 512 thr, warp 32x32, 4 stages ----
#define AS1 72
#define A_BY1 (128 * AS1 * 2)          // 18432
#define B_BY1 (64 * 136 * 2)           // 17408
#define STG1 (A_BY1 + 2 * B_BY1)       // 53248
#define SMEM1 (4 * STG1)               // 212992

// ---- GEMM2: CTA 128x128, KT=32, 256 thr, warp 64x32, 4 stages, 2 CTA/SM --
#define AS2 40
#define A_BY2 (128 * AS2 * 2)          // 10240
#define B_BY2 (32 * 136 * 2)           // 8704
#define STG2 (A_BY2 + B_BY2)           // 18944
#define SMEM2 (4 * STG2)               // 75776

// ---------------- device scratch ----------------
__device__ int    g_counts[NE];
__device__ int    g_rows[NE * CAP];
__device__ int    g_tok_e[TOK * 2];
__device__ int    g_tok_p[TOK * 2];
__device__ float  g_tok_w[TOK * 2];
__device__ __half g_xh[(size_t)TOK * DIM];
__device__ __half g_w1h[(size_t)NG * DIM * HID];
__device__ __half g_w2h[(size_t)NG * DIM * HID];
__device__ __half g_w3h[(size_t)NG * HID * DIM];
__device__ __half g_hh[(size_t)NG * CAP * HID];
__device__ float  g_y[(size_t)NG * CAP * DIM];

// ---------------- PTX helpers ----------------
__device__ __forceinline__ uint32_t smem_u32(const void* p) {
    uint32_t a;
    asm("{ .reg .u64 t; cvta.to.shared.u64 t, %1; cvt.u32.u64 %0, t; }"
        : "=r"(a) : "l"(p));
    return a;
}
__device__ __forceinline__ void cpa16(uint32_t dst, const void* src) {
    asm volatile("cp.async.cg.shared.global [%0], [%1], 16;"
                 :: "r"(dst), "l"(src) : "memory");
}
__device__ __forceinline__ void cpa16z(uint32_t dst, const void* src, int sz) {
    asm volatile("cp.async.cg.shared.global [%0], [%1], 16, %2;"
                 :: "r"(dst), "l"(src), "r"(sz) : "memory");
}
#define CP_COMMIT() asm volatile("cp.async.commit_group;" ::: "memory")
#define CP_WAIT(n)  asm volatile("cp.async.wait_group %0;" :: "n"(n) : "memory")

__device__ __forceinline__ void ldsm4(uint32_t* r, uint32_t addr) {
    asm volatile("ldmatrix.sync.aligned.m8n8.x4.shared.b16 {%0,%1,%2,%3}, [%4];"
                 : "=r"(r[0]), "=r"(r[1]), "=r"(r[2]), "=r"(r[3]) : "r"(addr));
}
__device__ __forceinline__ void ldsm4t(uint32_t* r, uint32_t addr) {
    asm volatile("ldmatrix.sync.aligned.m8n8.x4.trans.shared.b16 {%0,%1,%2,%3}, [%4];"
                 : "=r"(r[0]), "=r"(r[1]), "=r"(r[2]), "=r"(r[3]) : "r"(addr));
}
__device__ __forceinline__ void mma16(float* d, const uint32_t* a, const uint32_t* b) {
    asm volatile(
        "mma.sync.aligned.m16n8k16.row.col.f32.f16.f16.f32 "
        "{%0,%1,%2,%3}, {%4,%5,%6,%7}, {%8,%9}, {%0,%1,%2,%3};"
        : "+f"(d[0]), "+f"(d[1]), "+f"(d[2]), "+f"(d[3])
        : "r"(a[0]), "r"(a[1]), "r"(a[2]), "r"(a[3]), "r"(b[0]), "r"(b[1]));
}

// ---------------- 0) convert f32 -> f16 (serial, all 7 segments) ----------
__device__ __forceinline__ void cvt8(const float4* s4, uint4* d4, size_t i) {
    float4 a = s4[2 * i], b = s4[2 * i + 1];
    __half2 h0 = __floats2half2_rn(a.x, a.y);
    __half2 h1 = __floats2half2_rn(a.z, a.w);
    __half2 h2 = __floats2half2_rn(b.x, b.y);
    __half2 h3 = __floats2half2_rn(b.z, b.w);
    uint4 o;
    o.x = *(uint32_t*)&h0; o.y = *(uint32_t*)&h1;
    o.z = *(uint32_t*)&h2; o.w = *(uint32_t*)&h3;
    d4[i] = o;
}
__global__ __launch_bounds__(256) void convert_k(
    const float* __restrict__ x,
    const float* __restrict__ sw1, const float* __restrict__ sw2,
    const float* __restrict__ sw3,
    const float* __restrict__ w1, const float* __restrict__ w2,
    const float* __restrict__ w3) {
    int seg = blockIdx.y;
    const float* src; __half* dst; size_t cnt;
    switch (seg) {
        case 0: src = w1;  dst = g_w1h;                          cnt = (size_t)NE * DIM * HID; break;
        case 1: src = sw1; dst = g_w1h + (size_t)NE * DIM * HID; cnt = (size_t)DIM * HID;      break;
        case 2: src = w2;  dst = g_w2h;                          cnt = (size_t)NE * DIM * HID; break;
        case 3: src = sw2; dst = g_w2h + (size_t)NE * DIM * HID; cnt = (size_t)DIM * HID;      break;
        case 4: src = w3;  dst = g_w3h;                          cnt = (size_t)NE * HID * DIM; break;
        case 5: src = sw3; dst = g_w3h + (size_t)NE * HID * DIM; cnt = (size_t)HID * DIM;      break;
        default: src = x;  dst = g_xh;                           cnt = (size_t)TOK * DIM;      break;
    }
    size_t n8 = cnt >> 3;
    size_t i0 = (size_t)blockIdx.x * blockDim.x + threadIdx.x;
    size_t stride = (size_t)gridDim.x * blockDim.x;
    const float4* s4 = (const float4*)src;
    uint4* d4 = (uint4*)dst;
    size_t i = i0;
    for (; i + stride < n8; i += 2 * stride) {
        cvt8(s4, d4, i);
        cvt8(s4, d4, i + stride);
    }
    for (; i < n8; i += stride) cvt8(s4, d4, i);
}

// ---------------- 1) router ----------------
__global__ __launch_bounds__(256) void router_k(const float* __restrict__ x,
                                                const float* __restrict__ rw,
                                                float* __restrict__ logits) {
    int t = blockIdx.x;
    __shared__ float xs[DIM];
    __shared__ float lg[NE];
    int tid = threadIdx.x;
    for (int i = tid; i < DIM; i += 256) xs[i] = x[(size_t)t * DIM + i];
    __syncthreads();
    int w = tid >> 5, lane = tid & 31;
    const float* r = rw + w * DIM;
    float s = 0.f;
    for (int i = lane; i < DIM; i += 32) s += xs[i] * r[i];
    #pragma unroll
    for (int o = 16; o; o >>= 1) s += __shfl_down_sync(0xffffffffu, s, o);
    if (lane == 0) lg[w] = s;
    __syncthreads();
    if (tid == 0) {
        #pragma unroll
        for (int e = 0; e < NE; e++) logits[t * NE + e] = lg[e];
        int e0 = 0; float l0 = lg[0];
        for (int e = 1; e < NE; e++) if (lg[e] > l0) { l0 = lg[e]; e0 = e; }
        int e1 = -1; float l1 = -1e30f;
        for (int e = 0; e < NE; e++) if (e != e0 && lg[e] > l1) { l1 = lg[e]; e1 = e; }
        float w0 = 1.f / (1.f + __expf(l1 - l0));
        float w1 = 1.f - w0;
        int p0 = atomicAdd(&g_counts[e0], 1);
        int p1 = atomicAdd(&g_counts[e1], 1);
        g_rows[e0 * CAP + p0] = t;
        g_rows[e1 * CAP + p1] = t;
        g_tok_e[2*t] = e0; g_tok_e[2*t+1] = e1;
        g_tok_p[2*t] = p0; g_tok_p[2*t+1] = p1;
        g_tok_w[2*t] = w0; g_tok_w[2*t+1] = w1;
    }
}

// ------- 2) GEMM1 (fp16 mma, 512 thr, warp 32x32, KT=64, 4 stages) --------
__global__ __launch_bounds__(512, 1) void gemm1_tc() {
    int g = blockIdx.z;
    int n = (g == 8) ? TOK : g_counts[g];
    int row0 = blockIdx.x * 128;
    if (row0 >= n) return;
    int col0 = blockIdx.y * 128;
    const __half* B1g = g_w1h + (size_t)g * DIM * HID;
    const __half* B2g = g_w2h + (size_t)g * DIM * HID;

    extern __shared__ char dynb[];
    __shared__ int toks[128];
    int tid = threadIdx.x, lane = tid & 31, wid = tid >> 5;

    if (tid < 128) {
        int r = row0 + tid;
        toks[tid] = (r < n) ? ((g == 8) ? r : g_rows[g * CAP + r]) : -1;
    }
    __syncthreads();

    uint32_t sbase = smem_u32(dynb);
    int am = tid >> 2, aq = tid & 3;
    int atok = toks[am];
    const __half* asrc = g_xh + ((atok >= 0) ? (size_t)atok * DIM : 0) + aq * 16;
    int asz = (atok >= 0) ? 16 : 0;
    uint32_t adst = sbase + am * (AS1 * 2) + aq * 32;
    int brow = tid >> 3, bch = (tid & 7) * 2;
    const __half* b1src = B1g + (size_t)brow * HID + col0 + bch * 8;
    const __half* b2src = B2g + (size_t)brow * HID + col0 + bch * 8;
    uint32_t bdst = sbase + A_BY1 + brow * (136 * 2) + bch * 16;

    const int NC = DIM / 64;  // 16

    auto prefetch = [&](int c) {
        uint32_t so = (uint32_t)(c & 3) * STG1;
        cpa16z(adst + so,      asrc + c * 64,     asz);
        cpa16z(adst + so + 16, asrc + c * 64 + 8, asz);
        const __half* p1 = b1src + (size_t)(c * 64) * HID;
        const __half* p2 = b2src + (size_t)(c * 64) * HID;
        cpa16(bdst + so,                p1);
        cpa16(bdst + so + 16,           p1 + 8);
        cpa16(bdst + so + B_BY1,        p2);
        cpa16(bdst + so + B_BY1 + 16,   p2 + 8);
    };

    prefetch(0); CP_COMMIT();
    prefetch(1); CP_COMMIT();
    prefetch(2); CP_COMMIT();

    float acc1[2][4][4] = {};
    float acc2[2][4][4] = {};
    int wm = (wid & 3) * 32, wn = (wid >> 2) * 32;
    uint32_t aoff = ((wm + (lane & 15)) * AS1 + (lane >> 4) * 8) * 2;
    uint32_t boff = ((lane & 15) * 136 + wn + (lane >> 4) * 8) * 2;

    for (int c = 0; c < NC; c++) {
        CP_WAIT(2);
        __syncthreads();
        if (c + 3 < NC) prefetch(c + 3);
        CP_COMMIT();
        uint32_t As_u = sbase + (uint32_t)(c & 3) * STG1;
        uint32_t B1_u = As_u + A_BY1;
        uint32_t B2_u = B1_u + B_BY1;
        #pragma unroll
        for (int kk = 0; kk < 4; kk++) {
            uint32_t af[2][4];
            #pragma unroll
            for (int mf = 0; mf < 2; mf++)
                ldsm4(af[mf], As_u + aoff + mf * (16 * AS1 * 2) + kk * 32);
            #pragma unroll
            for (int nfp = 0; nfp < 2; nfp++) {
                uint32_t bb = boff + nfp * 32 + kk * (16 * 136 * 2);
                uint32_t b1[4], b2[4];
                ldsm4t(b1, B1_u + bb);
                ldsm4t(b2, B2_u + bb);
                #pragma unroll
                for (int mf = 0; mf < 2; mf++) {
                    mma16(acc1[mf][nfp * 2],     af[mf], b1);
                    mma16(acc1[mf][nfp * 2 + 1], af[mf], b1 + 2);
                    mma16(acc2[mf][nfp * 2],     af[mf], b2);
                    mma16(acc2[mf][nfp * 2 + 1], af[mf], b2 + 2);
                }
            }
        }
    }

    #pragma unroll
    for (int mf = 0; mf < 2; mf++) {
        #pragma unroll
        for (int h = 0; h < 2; h++) {
            int r = row0 + wm + mf * 16 + (lane >> 2) + h * 8;
            if (r < n) {
                __half* hp = g_hh + ((size_t)g * CAP + r) * HID + col0 + wn + (lane & 3) * 2;
                #pragma unroll
                for (int nf = 0; nf < 4; nf++) {
                    float a0 = acc1[mf][nf][h * 2], a1 = acc1[mf][nf][h * 2 + 1];
                    float s0 = a0 / (1.f + __expf(-a0));
                    float s1 = a1 / (1.f + __expf(-a1));
                    *(__half2*)(hp + nf * 8) =
                        __floats2half2_rn(s0 * acc2[mf][nf][h * 2],
                                          s1 * acc2[mf][nf][h * 2 + 1]);
                }
            }
        }
    }
}

// ------- 3) GEMM2 (fp16 mma, 256 thr, warp 64x32, KT=32, 4 st, 2 CTA) -----
__global__ __launch_bounds__(256, 2) void gemm2_tc() {
    int g = blockIdx.z;
    int n = (g == 8) ? TOK : g_counts[g];
    int row0 = blockIdx.x * 128;
    if (row0 >= n) return;
    int col0 = blockIdx.y * 128;
    const __half* Bg = g_w3h + (size_t)g * HID * DIM;

    extern __shared__ char dynb[];
    int tid = threadIdx.x, lane = tid & 31, wid = tid >> 5;
    uint32_t sbase = smem_u32(dynb);

    int am = tid >> 1, aq = (tid & 1) * 2;
    int ar = row0 + am;
    const __half* asrc = g_hh + ((ar < n) ? ((size_t)g * CAP + ar) * HID : 0) + aq * 8;
    int asz = (ar < n) ? 16 : 0;
    uint32_t adst = sbase + am * (AS2 * 2) + aq * 16;
    int brow = tid >> 3, bch = (tid & 7) * 2;
    const __half* bsrc = Bg + (size_t)brow * DIM + col0 + bch * 8;
    uint32_t bdst = sbase + A_BY2 + brow * (136 * 2) + bch * 16;

    const int NC = HID / 32;  // 128

    auto prefetch = [&](int c) {
        uint32_t so = (uint32_t)(c & 3) * STG2;
        cpa16z(adst + so,      asrc + c * 32,     asz);
        cpa16z(adst + so + 16, asrc + c * 32 + 8, asz);
        const __half* p = bsrc + (size_t)(c * 32) * DIM;
        cpa16(bdst + so,      p);
        cpa16(bdst + so + 16, p + 8);
    };

    prefetch(0); CP_COMMIT();
    prefetch(1); CP_COMMIT();
    prefetch(2); CP_COMMIT();

    float acc[4][4][4] = {};
    int wm = (wid & 1) * 64, wn = (wid >> 1) * 32;   // warp tile 64x32
    uint32_t aoff = ((wm + (lane & 15)) * AS2 + (lane >> 4) * 8) * 2;
    uint32_t boff = ((lane & 15) * 136 + wn + (lane >> 4) * 8) * 2;

    for (int c = 0; c < NC; c++) {
        CP_WAIT(2);
        __syncthreads();
        if (c + 3 < NC) prefetch(c + 3);
        CP_COMMIT();
        uint32_t As_u = sbase + (uint32_t)(c & 3) * STG2;
        uint32_t B_u  = As_u + A_BY2;
        #pragma unroll
        for (int kk = 0; kk < 2; kk++) {
            uint32_t af[4][4];
            #pragma unroll
            for (int mf = 0; mf < 4; mf++)
                ldsm4(af[mf], As_u + aoff + mf * (16 * AS2 * 2) + kk * 32);
            #pragma unroll
            for (int nfp = 0; nfp < 2; nfp++) {
                uint32_t bb = boff + nfp * 32 + kk * (16 * 136 * 2);
                uint32_t b[4];
                ldsm4t(b, B_u + bb);
                #pragma unroll
                for (int mf = 0; mf < 4; mf++) {
                    mma16(acc[mf][nfp * 2],     af[mf], b);
                    mma16(acc[mf][nfp * 2 + 1], af[mf], b + 2);
                }
            }
        }
    }

    #pragma unroll
    for (int mf = 0; mf < 4; mf++) {
        #pragma unroll
        for (int h = 0; h < 2; h++) {
            int r = row0 + wm + mf * 16 + (lane >> 2) + h * 8;
            if (r < n) {
                float* yp = g_y + ((size_t)g * CAP + r) * DIM + col0 + wn + (lane & 3) * 2;
                #pragma unroll
                for (int nf = 0; nf < 4; nf++)
                    *(float2*)(yp + nf * 8) =
                        make_float2(acc[mf][nf][h * 2], acc[mf][nf][h * 2 + 1]);
            }
        }
    }
}

// ---------------- 4) combine ----------------
__global__ __launch_bounds__(256) void combine_k(float* __restrict__ out) {
    int t = blockIdx.x;
    int tid = threadIdx.x;
    int e0 = g_tok_e[2*t], e1 = g_tok_e[2*t+1];
    int p0 = g_tok_p[2*t], p1 = g_tok_p[2*t+1];
    float w0 = g_tok_w[2*t], w1 = g_tok_w[2*t+1];
    const float4* ys = (const float4*)(g_y + ((size_t)8 * CAP + t) * DIM);
    const float4* y0 = (const float4*)(g_y + ((size_t)e0 * CAP + p0) * DIM);
    const float4* y1 = (const float4*)(g_y + ((size_t)e1 * CAP + p1) * DIM);
    float4* op = (float4*)(out + (size_t)t * DIM);
    float4 a = ys[tid], b = y0[tid], c = y1[tid];
    float4 o;
    o.x = a.x + w0 * b.x + w1 * c.x;
    o.y = a.y + w0 * b.y + w1 * c.y;
    o.z = a.z + w0 * b.z + w1 * c.z;
    o.w = a.w + w0 * b.w + w1 * c.w;
    op[tid] = o;
}

// ---------------- launch ----------------
extern "C" void kernel_launch(void* const* d_in, const int* in_sizes, int n_in,
                              void* d_out, int out_size) {
    const float* x   = (const float*)d_in[0];
    const float* sw1 = (const float*)d_in[1];
    const float* sw2 = (const float*)d_in[2];
    const float* sw3 = (const float*)d_in[3];
    const float* w1  = (const float*)d_in[4];
    const float* w2  = (const float*)d_in[5];
    const float* w3  = (const float*)d_in[6];
    const float* rw  = (const float*)d_in[7];
    float* out    = (float*)d_out;
    float* logits = out + (size_t)TOK * DIM;

    // One-time resources (first/correctness call allocates them inside the
    // harness's pre-capture baseline; capture call allocates nothing).
    static bool s_init = false;
    static cudaStream_t s3;
    static cudaEvent_t eM, e3;
    if (!s_init) {
        cudaStreamCreateWithFlags(&s3, cudaStreamNonBlocking);
        cudaEventCreateWithFlags(&eM, cudaEventDisableTiming);
        cudaEventCreateWithFlags(&e3, cudaEventDisableTiming);
        cudaFuncSetAttribute(gemm1_tc, cudaFuncAttributeMaxDynamicSharedMemorySize, SMEM1);
        cudaFuncSetAttribute(gemm2_tc, cudaFuncAttributeMaxDynamicSharedMemorySize, SMEM2);
        cudaMemsetAsync((void*)g_counts, 0, 1, s3);  // warm side-stream pool
        s_init = true;
    }

    void* cptr = nullptr;
    cudaGetSymbolAddress(&cptr, g_counts);
    cudaMemsetAsync(cptr, 0, NE * sizeof(int));

    // fork router (reads f32 x/rw + zeroed counts), overlapped with convert
    cudaEventRecord(eM, 0);
    cudaStreamWaitEvent(s3, eM, 0);
    router_k<<<TOK, 256, 0, s3>>>(x, rw, logits);
    cudaEventRecord(e3, s3);

    // serial full convert (all 7 segments)
    convert_k<<<dim3(864, 7), 256>>>(x, sw1, sw2, sw3, w1, w2, w3);

    // gemm1 needs router results + converted w1/w2/x
    cudaStreamWaitEvent(0, e3, 0);
    gemm1_tc<<<dim3(CAP / 128, HID / 128, NG), 512, SMEM1>>>();
    gemm2_tc<<<dim3(CAP / 128, DIM / 128, NG), 256, SMEM2>>>();
    combine_k<<<TOK, 256>>>(out);
}